// round 1
// baseline (speedup 1.0000x reference)
#include <cuda_runtime.h>
#include <cuda_bf16.h>

// Sparsemax over last dim, rows of N=1024 fp32.
// One CTA of 256 threads per row; row held in registers as float4/thread.
// tau found by Michelot fixed-point iteration (exact, no sort).

static constexpr int N = 1024;
static constexpr int THREADS = 256;   // 256 * 4 = 1024 elements

// Block-wide max reduce (256 threads, 8 warps)
__device__ __forceinline__ float block_reduce_max(float v, float* sh) {
    #pragma unroll
    for (int o = 16; o > 0; o >>= 1)
        v = fmaxf(v, __shfl_xor_sync(0xFFFFFFFFu, v, o));
    int w = threadIdx.x >> 5;
    if ((threadIdx.x & 31) == 0) sh[w] = v;
    __syncthreads();
    float r;
    if (threadIdx.x < 32) {
        float t = (threadIdx.x < (THREADS / 32)) ? sh[threadIdx.x] : -3.402823466e38f;
        #pragma unroll
        for (int o = 4; o > 0; o >>= 1)
            t = fmaxf(t, __shfl_xor_sync(0xFFFFFFFFu, t, o));
        if (threadIdx.x == 0) sh[0] = t;
    }
    __syncthreads();
    r = sh[0];
    __syncthreads();   // protect sh before next reuse
    return r;
}

// Block-wide (sum_a, sum_b) reduce
__device__ __forceinline__ float2 block_reduce_add2(float a, float b, float2* sh) {
    #pragma unroll
    for (int o = 16; o > 0; o >>= 1) {
        a += __shfl_xor_sync(0xFFFFFFFFu, a, o);
        b += __shfl_xor_sync(0xFFFFFFFFu, b, o);
    }
    int w = threadIdx.x >> 5;
    if ((threadIdx.x & 31) == 0) sh[w] = make_float2(a, b);
    __syncthreads();
    if (threadIdx.x < 32) {
        float2 t = (threadIdx.x < (THREADS / 32)) ? sh[threadIdx.x] : make_float2(0.f, 0.f);
        #pragma unroll
        for (int o = 4; o > 0; o >>= 1) {
            t.x += __shfl_xor_sync(0xFFFFFFFFu, t.x, o);
            t.y += __shfl_xor_sync(0xFFFFFFFFu, t.y, o);
        }
        if (threadIdx.x == 0) sh[0] = t;
    }
    __syncthreads();
    float2 r = sh[0];
    __syncthreads();
    return r;
}

__global__ __launch_bounds__(THREADS, 8)
void sparsemax_kernel(const float* __restrict__ x, float* __restrict__ out) {
    __shared__ float2 sh2[THREADS / 32];

    const size_t row_base = (size_t)blockIdx.x * N;
    const float4* __restrict__ xr  = reinterpret_cast<const float4*>(x + row_base);
    float4*       __restrict__ orow = reinterpret_cast<float4*>(out + row_base);

    float4 v = xr[threadIdx.x];

    // 1) row max
    float m = fmaxf(fmaxf(v.x, v.y), fmaxf(v.z, v.w));
    m = block_reduce_max(m, reinterpret_cast<float*>(sh2));

    // 2) shift
    v.x -= m; v.y -= m; v.z -= m; v.w -= m;

    // 3) initial tau = (sum(z) - 1) / n
    float s = (v.x + v.y) + (v.z + v.w);
    float2 r0 = block_reduce_add2(s, 0.f, sh2);
    float tau = (r0.x - 1.0f) / (float)N;
    float prev_k = (float)N;

    // 4) Michelot fixed-point: tau <- (sum_{z>tau} z - 1) / |{z>tau}|
    #pragma unroll 1
    for (int it = 0; it < 64; ++it) {
        float ps = 0.f, pk = 0.f;
        if (v.x > tau) { ps += v.x; pk += 1.f; }
        if (v.y > tau) { ps += v.y; pk += 1.f; }
        if (v.z > tau) { ps += v.z; pk += 1.f; }
        if (v.w > tau) { ps += v.w; pk += 1.f; }
        float2 r = block_reduce_add2(ps, pk, sh2);
        // k >= 1 always: the max element (z=0) satisfies 0 > tau (tau < 0 since sum<=1 path);
        // guard anyway against k==0 pathologies.
        float k = (r.y > 0.f) ? r.y : 1.f;
        float nt = (r.x - 1.0f) / k;
        bool done = (nt == tau) && (k == prev_k);
        tau = nt;
        prev_k = k;
        if (done) break;
    }

    // 5) output max(z - tau, 0)
    float4 o;
    o.x = fmaxf(v.x - tau, 0.f);
    o.y = fmaxf(v.y - tau, 0.f);
    o.z = fmaxf(v.z - tau, 0.f);
    o.w = fmaxf(v.w - tau, 0.f);
    orow[threadIdx.x] = o;
}

extern "C" void kernel_launch(void* const* d_in, const int* in_sizes, int n_in,
                              void* d_out, int out_size) {
    const float* x = (const float*)d_in[0];
    float* out = (float*)d_out;
    int rows = in_sizes[0] / N;
    sparsemax_kernel<<<rows, THREADS>>>(x, out);
}

// round 2
// speedup vs baseline: 3.9565x; 3.9565x over previous
#include <cuda_runtime.h>
#include <cuda_bf16.h>

// Sparsemax over last dim, rows of N=1024 fp32.
// One WARP per row; 32 elements/thread in registers.
// tau via candidate compaction (support subset of {x > max-1}) + exact
// closed-form rank test on the tiny candidate set. No block barriers.

static constexpr int N = 1024;
static constexpr int THREADS = 256;            // 8 warps -> 8 rows per block
static constexpr int WARPS = THREADS / 32;
static constexpr int EPT = N / 32;             // 32 elements per thread
static constexpr int CAP = 128;                // candidate buffer per warp

__global__ __launch_bounds__(THREADS, 4)
void sparsemax_kernel(const float* __restrict__ x, float* __restrict__ out) {
    __shared__ float cand[WARPS][CAP];

    const int lane = threadIdx.x & 31;
    const int w    = threadIdx.x >> 5;
    const int row  = blockIdx.x * WARPS + w;
    const size_t base = (size_t)row * N;

    const float4* __restrict__ xr = reinterpret_cast<const float4*>(x + base);
    float4*       __restrict__ orw = reinterpret_cast<float4*>(out + base);

    // ---- load row: 8 x float4 per thread, coalesced, front-batched ----
    float4 d[EPT / 4];
    #pragma unroll
    for (int i = 0; i < EPT / 4; ++i) d[i] = xr[lane + 32 * i];

    // ---- warp max ----
    float m = -3.402823466e38f;
    #pragma unroll
    for (int i = 0; i < EPT / 4; ++i) {
        m = fmaxf(m, fmaxf(fmaxf(d[i].x, d[i].y), fmaxf(d[i].z, d[i].w)));
    }
    #pragma unroll
    for (int o = 16; o > 0; o >>= 1)
        m = fmaxf(m, __shfl_xor_sync(0xFFFFFFFFu, m, o));

    // tau in [-1, 0): support subset of {x > m - 1}
    const float thr = m - 1.0f;

    // ---- deterministic ballot compaction of candidates (z = x - m) ----
    int cbase = 0;
    #pragma unroll
    for (int i = 0; i < EPT / 4; ++i) {
        const float vv[4] = { d[i].x, d[i].y, d[i].z, d[i].w };
        #pragma unroll
        for (int j = 0; j < 4; ++j) {
            bool p = vv[j] > thr;
            unsigned mask = __ballot_sync(0xFFFFFFFFu, p);
            if (p) {
                int pos = cbase + __popc(mask & ((1u << lane) - 1u));
                if (pos < CAP) cand[w][pos] = vv[j] - m;
            }
            cbase += __popc(mask);
        }
    }
    __syncwarp();
    const int c = cbase;   // total candidates (same value in all lanes)

    float tau;
    if (c <= CAP) {
        // ---- exact closed-form: for each candidate, rank r and prefix sum S
        // over the (value desc, slot asc) total order; k = max r with
        // 1 + r*v > S; tau = (S_k - 1)/k. Valid because is_gt is a prefix
        // indicator and support is within the candidate prefix.
        float best_r = 0.0f, best_tau = 0.0f;
        for (int slot = lane; slot < c; slot += 32) {
            const float v = cand[w][slot];
            float S = 0.0f, r = 0.0f;
            for (int j = 0; j < c; ++j) {
                const float u = cand[w][j];
                bool ge = (u > v) || (u == v && j <= slot);
                if (ge) { S += u; r += 1.0f; }
            }
            if (1.0f + r * v > S && r > best_r) {
                best_r = r;
                best_tau = (S - 1.0f) / r;
            }
        }
        #pragma unroll
        for (int o = 16; o > 0; o >>= 1) {
            float rr = __shfl_xor_sync(0xFFFFFFFFu, best_r, o);
            float tt = __shfl_xor_sync(0xFFFFFFFFu, best_tau, o);
            if (rr > best_r) { best_r = rr; best_tau = tt; }
        }
        tau = best_tau;
    } else {
        // ---- fallback (essentially never taken): warp-local Michelot ----
        float s = 0.0f;
        #pragma unroll
        for (int i = 0; i < EPT / 4; ++i)
            s += ((d[i].x - m) + (d[i].y - m)) + ((d[i].z - m) + (d[i].w - m));
        #pragma unroll
        for (int o = 16; o > 0; o >>= 1)
            s += __shfl_xor_sync(0xFFFFFFFFu, s, o);
        tau = (s - 1.0f) / (float)N;
        float prev_k = (float)N;
        #pragma unroll 1
        for (int it = 0; it < 64; ++it) {
            float ps = 0.0f, pk = 0.0f;
            #pragma unroll
            for (int i = 0; i < EPT / 4; ++i) {
                const float vv[4] = { d[i].x - m, d[i].y - m, d[i].z - m, d[i].w - m };
                #pragma unroll
                for (int j = 0; j < 4; ++j)
                    if (vv[j] > tau) { ps += vv[j]; pk += 1.0f; }
            }
            #pragma unroll
            for (int o = 16; o > 0; o >>= 1) {
                ps += __shfl_xor_sync(0xFFFFFFFFu, ps, o);
                pk += __shfl_xor_sync(0xFFFFFFFFu, pk, o);
            }
            float k = (pk > 0.0f) ? pk : 1.0f;
            float nt = (ps - 1.0f) / k;
            bool done = (nt == tau) && (k == prev_k);
            tau = nt;
            prev_k = k;
            if (done) break;
        }
    }

    // ---- output: max(x - (m + tau), 0) ----
    const float t2 = m + tau;
    #pragma unroll
    for (int i = 0; i < EPT / 4; ++i) {
        float4 o;
        o.x = fmaxf(d[i].x - t2, 0.0f);
        o.y = fmaxf(d[i].y - t2, 0.0f);
        o.z = fmaxf(d[i].z - t2, 0.0f);
        o.w = fmaxf(d[i].w - t2, 0.0f);
        orw[lane + 32 * i] = o;
    }
}

extern "C" void kernel_launch(void* const* d_in, const int* in_sizes, int n_in,
                              void* d_out, int out_size) {
    const float* x = (const float*)d_in[0];
    float* out = (float*)d_out;
    int rows = in_sizes[0] / N;
    sparsemax_kernel<<<rows / WARPS, THREADS>>>(x, out);
}